// round 1
// baseline (speedup 1.0000x reference)
#include <cuda_runtime.h>

#define D 128
#define S 12

// Scratch (allocation-free rule: __device__ globals)
__device__ float g_agg_a[64 * 50  * 128];   // aggregate hop-1 level-0  [B*50 ,D]
__device__ float g_agg_b[64 * 600 * 128];   // aggregate hop-1 level-1  [B*600,D]
__device__ float g_agg_c[64 * 50  * 128];   // aggregate hop-2          [B*50 ,D]

// One block per (b,n). item:[N,D], nbh:[N,S,D] flat, nbw:[N,S] flat.
__global__ __launch_bounds__(128) void agg_kernel(
    const float* __restrict__ item, const float* __restrict__ nbh,
    const float* __restrict__ nbw,  const float* __restrict__ w1,
    const float* __restrict__ w2,   float* __restrict__ out)
{
    const int n = blockIdx.x;
    const int t = threadIdx.x;
    const int lane = t & 31, warp = t >> 5;

    __shared__ float sh_nbh[S * D];                    // neighbor tile
    __shared__ __align__(16) float sh_feat[(D + 1) * S]; // feat transposed [k][s]
    __shared__ float sh_item[D];
    __shared__ float sh_nbw[S];
    __shared__ float sh_red[4][S];
    __shared__ float sh_alpha[S];

    // ---- stage inputs ----
    const float* nbh_p = nbh + (size_t)n * (S * D);
    #pragma unroll
    for (int i = 0; i < S; i++) sh_nbh[i * D + t] = nbh_p[i * D + t];
    sh_item[t] = item[(size_t)n * D + t];
    if (t < S) sh_nbw[t] = nbw[(size_t)n * S + t];
    __syncthreads();

    // ---- build feat[k][s]: k<D -> item[k]*nbh[s][k]; k==D -> nbw[s] ----
    {
        float it = sh_item[t];
        #pragma unroll
        for (int s = 0; s < S; s++) sh_feat[t * S + s] = it * sh_nbh[s * D + t];
        if (t < S) sh_feat[D * S + t] = sh_nbw[t];
    }
    __syncthreads();

    // ---- alpha_pre[s][t] = sum_k feat[s][k] * w1[k][t]  (thread t = out col) ----
    float acc[S];
    #pragma unroll
    for (int s = 0; s < S; s++) acc[s] = 0.f;

    const float* w1c = w1 + t;
    #pragma unroll 4
    for (int k = 0; k <= D; k++) {
        float wv = __ldg(&w1c[k * D]);
        const float4* f = (const float4*)&sh_feat[k * S];
        float4 f0 = f[0], f1 = f[1], f2 = f[2];
        acc[0]  = fmaf(f0.x, wv, acc[0]);  acc[1]  = fmaf(f0.y, wv, acc[1]);
        acc[2]  = fmaf(f0.z, wv, acc[2]);  acc[3]  = fmaf(f0.w, wv, acc[3]);
        acc[4]  = fmaf(f1.x, wv, acc[4]);  acc[5]  = fmaf(f1.y, wv, acc[5]);
        acc[6]  = fmaf(f1.z, wv, acc[6]);  acc[7]  = fmaf(f1.w, wv, acc[7]);
        acc[8]  = fmaf(f2.x, wv, acc[8]);  acc[9]  = fmaf(f2.y, wv, acc[9]);
        acc[10] = fmaf(f2.z, wv, acc[10]); acc[11] = fmaf(f2.w, wv, acc[11]);
    }

    // ---- logits: leaky_relu then dot with w2 (reduce over t) ----
    float w2t = w2[t];
    #pragma unroll
    for (int s = 0; s < S; s++) {
        float v = acc[s];
        v = v > 0.f ? v : 0.2f * v;
        float p = v * w2t;
        #pragma unroll
        for (int o = 16; o > 0; o >>= 1) p += __shfl_xor_sync(0xffffffffu, p, o);
        if (lane == 0) sh_red[warp][s] = p;
    }
    __syncthreads();

    // ---- softmax over S (tiny; single thread) ----
    if (t == 0) {
        float logit[S]; float m = -1e30f;
        #pragma unroll
        for (int s = 0; s < S; s++) {
            logit[s] = sh_red[0][s] + sh_red[1][s] + sh_red[2][s] + sh_red[3][s];
            m = fmaxf(m, logit[s]);
        }
        float sum = 0.f;
        #pragma unroll
        for (int s = 0; s < S; s++) { float e = expf(logit[s] - m); sh_alpha[s] = e; sum += e; }
        float inv = 1.f / sum;
        #pragma unroll
        for (int s = 0; s < S; s++) sh_alpha[s] *= inv;
    }
    __syncthreads();

    // ---- weighted sum of neighbors ----
    float o = 0.f;
    #pragma unroll
    for (int s = 0; s < S; s++) o = fmaf(sh_alpha[s], sh_nbh[s * D + t], o);
    out[(size_t)n * D + t] = o;
}

// Final gating: weight = sigmoid(hidden@w3 + agg@w4); out = lerp
__global__ __launch_bounds__(128) void final_kernel(
    const float* __restrict__ hidden, const float* __restrict__ agg_a,
    const float* __restrict__ agg_c,  const float* __restrict__ w3,
    const float* __restrict__ w4,     const float* __restrict__ sv,
    float* __restrict__ out)
{
    const int n = blockIdx.x;
    const int t = threadIdx.x;
    __shared__ float sh_h[D], sh_g[D];

    const float s0 = sv[0], s1 = sv[1];
    float h = hidden[(size_t)n * D + t];
    float g = s0 * agg_a[(size_t)n * D + t] + s1 * agg_c[(size_t)n * D + t];
    sh_h[t] = h; sh_g[t] = g;
    __syncthreads();

    float a0 = 0.f, a1 = 0.f;
    #pragma unroll 4
    for (int k = 0; k < D; k++) {
        a0 = fmaf(sh_h[k], __ldg(&w3[k * D + t]), a0);
        a1 = fmaf(sh_g[k], __ldg(&w4[k * D + t]), a1);
    }
    float wgt = 1.f / (1.f + expf(-(a0 + a1)));
    out[(size_t)n * D + t] = (1.f - wgt) * h + wgt * g;
}

extern "C" void kernel_launch(void* const* d_in, const int* in_sizes, int n_in,
                              void* d_out, int out_size)
{
    const float* hidden = (const float*)d_in[0];
    const float* nh1    = (const float*)d_in[1];
    const float* nh2    = (const float*)d_in[2];
    const float* nw0    = (const float*)d_in[3];
    const float* nw1    = (const float*)d_in[4];
    const float* w1     = (const float*)d_in[5];
    const float* w2     = (const float*)d_in[6];
    const float* w3     = (const float*)d_in[7];
    const float* w4     = (const float*)d_in[8];
    const float* sv     = (const float*)d_in[9];
    float* out = (float*)d_out;

    const int N0 = in_sizes[0] / D;   // B*L   = 3200
    const int N1 = in_sizes[1] / D;   // B*L*S = 38400

    float *agg_a, *agg_b, *agg_c;
    cudaGetSymbolAddress((void**)&agg_a, g_agg_a);
    cudaGetSymbolAddress((void**)&agg_b, g_agg_b);
    cudaGetSymbolAddress((void**)&agg_c, g_agg_c);

    // hop 1
    agg_kernel<<<N0, 128>>>(hidden, nh1, nw0, w1, w2, agg_a);
    agg_kernel<<<N1, 128>>>(nh1,    nh2, nw1, w1, w2, agg_b);
    // hop 2
    agg_kernel<<<N0, 128>>>(agg_a,  agg_b, nw0, w1, w2, agg_c);
    // gate
    final_kernel<<<N0, 128>>>(hidden, agg_a, agg_c, w3, w4, sv, out);
}

// round 2
// speedup vs baseline: 1.0296x; 1.0296x over previous
#include <cuda_runtime.h>

#define D 128
#define S 12

// Scratch (allocation-free rule: __device__ globals)
__device__ float g_agg_a[64 * 50  * 128];   // hop-1 level-0  [B*50 ,D]
__device__ float g_agg_b[64 * 600 * 128];   // hop-1 level-1  [B*600,D]
__device__ float g_agg_c[64 * 50  * 128];   // hop-2          [B*50 ,D]

#define FMA2(acc, a, b) \
    asm("fma.rn.f32x2 %0, %1, %2, %0;" : "+l"(acc) : "l"(a), "l"(b))

__device__ __forceinline__ unsigned long long dup_f32(float v) {
    unsigned u = __float_as_uint(v);
    unsigned long long p;
    asm("mov.b64 %0, {%1, %1};" : "=l"(p) : "r"(u));
    return p;
}
__device__ __forceinline__ unsigned long long pack_f32(float lo, float hi) {
    unsigned long long p;
    asm("mov.b64 %0, {%1, %2};" : "=l"(p) : "r"(__float_as_uint(lo)), "r"(__float_as_uint(hi)));
    return p;
}
__device__ __forceinline__ void unpack_f32(unsigned long long p, float& lo, float& hi) {
    asm("mov.b64 {%0, %1}, %2;" : "=f"(lo), "=f"(hi) : "l"(p));
}

// One block per (b,n). item:[N,D], nbh:[N,S,D] flat, nbw:[N,S] flat.
__global__ __launch_bounds__(128) void agg_kernel(
    const float* __restrict__ item, const float* __restrict__ nbh,
    const float* __restrict__ nbw,  const float* __restrict__ w1,
    const float* __restrict__ w2,   float* __restrict__ out)
{
    const int n = blockIdx.x;
    const int t = threadIdx.x;
    const int lane = t & 31, warp = t >> 5;

    __shared__ __align__(16) float sh_nbh[S * D];          // neighbor tile
    __shared__ __align__(16) float sh_feat[(D + 1) * S];   // feat transposed [k][s]
    __shared__ float sh_item[D];
    __shared__ float sh_red[4][S];
    __shared__ float sh_alpha[S];

    // ---- stage inputs (vectorized) ----
    {
        const float4* src = (const float4*)(nbh + (size_t)n * (S * D));
        float4* dst = (float4*)sh_nbh;
        #pragma unroll
        for (int i = 0; i < (S * D) / 4 / 128; i++)  // 3 iters
            dst[t + i * 128] = src[t + i * 128];
        sh_item[t] = item[(size_t)n * D + t];
        if (t < S) sh_feat[D * S + t] = nbw[(size_t)n * S + t];  // k==128 row
    }
    __syncthreads();

    // ---- build feat[k][s] = item[k]*nbh[s][k] for k<D ----
    {
        float it = sh_item[t];
        #pragma unroll
        for (int s = 0; s < S; s++) sh_feat[t * S + s] = it * sh_nbh[s * D + t];
    }
    __syncthreads();

    // ---- alpha_pre[s][t] = sum_k feat[s][k]*w1[k][t], packed f32x2 over s ----
    unsigned long long acc0 = 0, acc1 = 0, acc2 = 0, acc3 = 0, acc4 = 0, acc5 = 0;
    const float* w1c = w1 + t;
    #pragma unroll 4
    for (int k = 0; k < D + 1; k++) {
        unsigned long long wp = dup_f32(__ldg(&w1c[k * D]));
        const ulonglong2* f = (const ulonglong2*)&sh_feat[k * S];
        ulonglong2 fa = f[0], fb = f[1], fc = f[2];   // 3x LDS.128 broadcast
        FMA2(acc0, fa.x, wp);  FMA2(acc1, fa.y, wp);
        FMA2(acc2, fb.x, wp);  FMA2(acc3, fb.y, wp);
        FMA2(acc4, fc.x, wp);  FMA2(acc5, fc.y, wp);
    }

    // ---- leaky_relu, dot with w2 (reduce over t) ----
    float v[S];
    unpack_f32(acc0, v[0], v[1]);   unpack_f32(acc1, v[2], v[3]);
    unpack_f32(acc2, v[4], v[5]);   unpack_f32(acc3, v[6], v[7]);
    unpack_f32(acc4, v[8], v[9]);   unpack_f32(acc5, v[10], v[11]);

    float w2t = w2[t];
    float p[S];
    #pragma unroll
    for (int s = 0; s < S; s++) {
        float x = v[s];
        x = x > 0.f ? x : 0.2f * x;
        p[s] = x * w2t;
    }
    #pragma unroll
    for (int o = 16; o > 0; o >>= 1) {
        #pragma unroll
        for (int s = 0; s < S; s++) p[s] += __shfl_xor_sync(0xffffffffu, p[s], o);
    }
    if (lane == 0) {
        #pragma unroll
        for (int s = 0; s < S; s++) sh_red[warp][s] = p[s];
    }
    __syncthreads();

    // ---- softmax over S (half-warp parallel in warp 0) ----
    if (warp == 0) {
        float logit = (lane < S)
            ? sh_red[0][lane] + sh_red[1][lane] + sh_red[2][lane] + sh_red[3][lane]
            : -1e30f;
        float m = logit;
        #pragma unroll
        for (int o = 8; o > 0; o >>= 1) m = fmaxf(m, __shfl_xor_sync(0xffffffffu, m, o, 16));
        float e = __expf(logit - m);
        if (lane >= S) e = 0.f;
        float sum = e;
        #pragma unroll
        for (int o = 8; o > 0; o >>= 1) sum += __shfl_xor_sync(0xffffffffu, sum, o, 16);
        if (lane < S) sh_alpha[lane] = e / sum;
    }
    __syncthreads();

    // ---- weighted sum of neighbors ----
    float o = 0.f;
    #pragma unroll
    for (int s = 0; s < S; s++) o = fmaf(sh_alpha[s], sh_nbh[s * D + t], o);
    out[(size_t)n * D + t] = o;
}

// Final gating: weight = sigmoid(hidden@w3 + agg@w4); out = lerp
__global__ __launch_bounds__(128) void final_kernel(
    const float* __restrict__ hidden, const float* __restrict__ agg_a,
    const float* __restrict__ agg_c,  const float* __restrict__ w3,
    const float* __restrict__ w4,     const float* __restrict__ sv,
    float* __restrict__ out)
{
    const int n = blockIdx.x;
    const int t = threadIdx.x;
    __shared__ unsigned long long sh_hg[D];   // packed (h,g) per k

    const float s0 = sv[0], s1 = sv[1];
    float h = hidden[(size_t)n * D + t];
    float g = s0 * agg_a[(size_t)n * D + t] + s1 * agg_c[(size_t)n * D + t];
    sh_hg[t] = pack_f32(h, g);
    __syncthreads();

    // packed: acc = sum_k {h[k],g[k]} * {w3[k][t],w4[k][t]}
    unsigned long long acc = 0;
    const float* w3c = w3 + t;
    const float* w4c = w4 + t;
    #pragma unroll 4
    for (int k = 0; k < D; k++) {
        unsigned long long wp = pack_f32(__ldg(&w3c[k * D]), __ldg(&w4c[k * D]));
        FMA2(acc, sh_hg[k], wp);
    }
    float a0, a1;
    unpack_f32(acc, a0, a1);
    float wgt = 1.f / (1.f + __expf(-(a0 + a1)));
    out[(size_t)n * D + t] = (1.f - wgt) * h + wgt * g;
}

extern "C" void kernel_launch(void* const* d_in, const int* in_sizes, int n_in,
                              void* d_out, int out_size)
{
    const float* hidden = (const float*)d_in[0];
    const float* nh1    = (const float*)d_in[1];
    const float* nh2    = (const float*)d_in[2];
    const float* nw0    = (const float*)d_in[3];
    const float* nw1    = (const float*)d_in[4];
    const float* w1     = (const float*)d_in[5];
    const float* w2     = (const float*)d_in[6];
    const float* w3     = (const float*)d_in[7];
    const float* w4     = (const float*)d_in[8];
    const float* sv     = (const float*)d_in[9];
    float* out = (float*)d_out;

    const int N0 = in_sizes[0] / D;   // B*L   = 3200
    const int N1 = in_sizes[1] / D;   // B*L*S = 38400

    float *agg_a, *agg_b, *agg_c;
    cudaGetSymbolAddress((void**)&agg_a, g_agg_a);
    cudaGetSymbolAddress((void**)&agg_b, g_agg_b);
    cudaGetSymbolAddress((void**)&agg_c, g_agg_c);

    // hop 1
    agg_kernel<<<N0, 128>>>(hidden, nh1, nw0, w1, w2, agg_a);
    agg_kernel<<<N1, 128>>>(nh1,    nh2, nw1, w1, w2, agg_b);
    // hop 2
    agg_kernel<<<N0, 128>>>(agg_a,  agg_b, nw0, w1, w2, agg_c);
    // gate
    final_kernel<<<N0, 128>>>(hidden, agg_a, agg_c, w3, w4, sv, out);
}

// round 3
// speedup vs baseline: 1.4459x; 1.4043x over previous
#include <cuda_runtime.h>

#define D 128
#define S 12

// Scratch (allocation-free rule: __device__ globals)
__device__ float g_agg_a[64 * 50  * 128];   // hop-1 level-0  [B*50 ,D]
__device__ float g_agg_b[64 * 600 * 128];   // hop-1 level-1  [B*600,D]
__device__ float g_agg_c[64 * 50  * 128];   // hop-2          [B*50 ,D]

#define FMA2(acc, a, b) \
    asm("fma.rn.f32x2 %0, %1, %2, %0;" : "+l"(acc) : "l"(a), "l"(b))

__device__ __forceinline__ unsigned long long dup_f32(float v) {
    unsigned u = __float_as_uint(v);
    unsigned long long p;
    asm("mov.b64 %0, {%1, %1};" : "=l"(p) : "r"(u));
    return p;
}
__device__ __forceinline__ unsigned long long pack_f32(float lo, float hi) {
    unsigned long long p;
    asm("mov.b64 %0, {%1, %2};" : "=l"(p) : "r"(__float_as_uint(lo)), "r"(__float_as_uint(hi)));
    return p;
}
__device__ __forceinline__ void unpack_f32(unsigned long long p, float& lo, float& hi) {
    asm("mov.b64 {%0, %1}, %2;" : "=f"(lo), "=f"(hi) : "l"(p));
}

// Warp-per-item. Block = 64 threads = 2 items. Lane owns cols lane+32j, j=0..3.
__global__ __launch_bounds__(64) void agg_kernel(
    const float* __restrict__ item, const float* __restrict__ nbh,
    const float* __restrict__ nbw,  const float* __restrict__ w1,
    const float* __restrict__ w2,   float* __restrict__ out)
{
    const int lane = threadIdx.x & 31;
    const int warp = threadIdx.x >> 5;
    const int n = blockIdx.x * 2 + warp;

    __shared__ __align__(16) float sh_nbh [2][S * D];         // 6 KB each
    __shared__ __align__(16) float sh_feat[2][(D + 1) * S + 4]; // feat [k][s], 48B rows

    float* nb = sh_nbh[warp];
    float* ft = sh_feat[warp];

    // ---- stage neighbor tile (12x128 fp32, vectorized) ----
    {
        const float4* src = (const float4*)(nbh + (size_t)n * (S * D));
        float4* dst = (float4*)nb;
        #pragma unroll
        for (int i = 0; i < 12; i++) dst[lane + 32 * i] = src[lane + 32 * i];
        if (lane < S) ft[D * S + lane] = nbw[(size_t)n * S + lane];  // bias row k==128
    }
    __syncwarp();

    // ---- build feat[k][s] = item[k] * nbh[s][k]; lane builds rows k=lane+32j ----
    #pragma unroll
    for (int j = 0; j < 4; j++) {
        const int k = lane + 32 * j;
        const float itk = item[(size_t)n * D + k];
        float r[S];
        #pragma unroll
        for (int s = 0; s < S; s++) r[s] = itk * nb[s * D + k];  // bank k%32=lane, no conflict
        float4* frow = (float4*)&ft[k * S];
        frow[0] = make_float4(r[0], r[1], r[2],  r[3]);
        frow[1] = make_float4(r[4], r[5], r[6],  r[7]);
        frow[2] = make_float4(r[8], r[9], r[10], r[11]);
    }
    __syncwarp();

    // ---- GEMV: acc[j][p] packs s-pair p for column c_j = lane+32j ----
    unsigned long long acc[4][6];
    #pragma unroll
    for (int j = 0; j < 4; j++)
        #pragma unroll
        for (int p = 0; p < 6; p++) acc[j][p] = 0ULL;

    #pragma unroll 3
    for (int k = 0; k < D + 1; k++) {
        const float* wr = w1 + (size_t)k * D + lane;
        unsigned long long w0 = dup_f32(__ldg(wr));
        unsigned long long w1d = dup_f32(__ldg(wr + 32));
        unsigned long long w2d = dup_f32(__ldg(wr + 64));
        unsigned long long w3d = dup_f32(__ldg(wr + 96));
        const ulonglong2* f = (const ulonglong2*)&ft[k * S];
        ulonglong2 fa = f[0], fb = f[1], fc = f[2];  // broadcast LDS.128 x3
        FMA2(acc[0][0], fa.x, w0);  FMA2(acc[0][1], fa.y, w0);
        FMA2(acc[0][2], fb.x, w0);  FMA2(acc[0][3], fb.y, w0);
        FMA2(acc[0][4], fc.x, w0);  FMA2(acc[0][5], fc.y, w0);
        FMA2(acc[1][0], fa.x, w1d); FMA2(acc[1][1], fa.y, w1d);
        FMA2(acc[1][2], fb.x, w1d); FMA2(acc[1][3], fb.y, w1d);
        FMA2(acc[1][4], fc.x, w1d); FMA2(acc[1][5], fc.y, w1d);
        FMA2(acc[2][0], fa.x, w2d); FMA2(acc[2][1], fa.y, w2d);
        FMA2(acc[2][2], fb.x, w2d); FMA2(acc[2][3], fb.y, w2d);
        FMA2(acc[2][4], fc.x, w2d); FMA2(acc[2][5], fc.y, w2d);
        FMA2(acc[3][0], fa.x, w3d); FMA2(acc[3][1], fa.y, w3d);
        FMA2(acc[3][2], fb.x, w3d); FMA2(acc[3][3], fb.y, w3d);
        FMA2(acc[3][4], fc.x, w3d); FMA2(acc[3][5], fc.y, w3d);
    }

    // ---- logits: leaky_relu, * w2[col], sum over cols (intra-warp only) ----
    float w2c[4];
    #pragma unroll
    for (int j = 0; j < 4; j++) w2c[j] = __ldg(&w2[lane + 32 * j]);

    float logit[S];
    #pragma unroll
    for (int p = 0; p < 6; p++) {
        float l0 = 0.f, l1 = 0.f;
        #pragma unroll
        for (int j = 0; j < 4; j++) {
            float lo, hi;
            unpack_f32(acc[j][p], lo, hi);
            lo = lo > 0.f ? lo : 0.2f * lo;
            hi = hi > 0.f ? hi : 0.2f * hi;
            l0 = fmaf(lo, w2c[j], l0);
            l1 = fmaf(hi, w2c[j], l1);
        }
        logit[2 * p] = l0;
        logit[2 * p + 1] = l1;
    }
    #pragma unroll
    for (int o = 16; o > 0; o >>= 1) {
        #pragma unroll
        for (int s = 0; s < S; s++)
            logit[s] += __shfl_xor_sync(0xffffffffu, logit[s], o);
    }

    // ---- softmax over S, register-resident, redundant per lane ----
    float m = logit[0];
    #pragma unroll
    for (int s = 1; s < S; s++) m = fmaxf(m, logit[s]);
    float e[S]; float sum = 0.f;
    #pragma unroll
    for (int s = 0; s < S; s++) { e[s] = __expf(logit[s] - m); sum += e[s]; }
    const float inv = 1.f / sum;
    float a[S];
    #pragma unroll
    for (int s = 0; s < S; s++) a[s] = e[s] * inv;

    // ---- weighted sum of neighbors ----
    #pragma unroll
    for (int j = 0; j < 4; j++) {
        const int c = lane + 32 * j;
        float o = 0.f;
        #pragma unroll
        for (int s = 0; s < S; s++) o = fmaf(a[s], nb[s * D + c], o);
        out[(size_t)n * D + c] = o;
    }
}

// Final gating, warp-per-item: weight = sigmoid(hidden@w3 + agg@w4); lerp.
__global__ __launch_bounds__(128) void final_kernel(
    const float* __restrict__ hidden, const float* __restrict__ agg_a,
    const float* __restrict__ agg_c,  const float* __restrict__ w3,
    const float* __restrict__ w4,     const float* __restrict__ sv,
    float* __restrict__ out)
{
    const int lane = threadIdx.x & 31;
    const int warp = threadIdx.x >> 5;
    const int n = blockIdx.x * 4 + warp;

    __shared__ unsigned long long sh_hg[4][D];

    const float s0 = sv[0], s1 = sv[1];
    float h[4], g[4];
    #pragma unroll
    for (int j = 0; j < 4; j++) {
        const int c = lane + 32 * j;
        h[j] = hidden[(size_t)n * D + c];
        g[j] = s0 * agg_a[(size_t)n * D + c] + s1 * agg_c[(size_t)n * D + c];
        sh_hg[warp][c] = pack_f32(h[j], g[j]);
    }
    __syncwarp();

    unsigned long long acc[4] = {0, 0, 0, 0};
    #pragma unroll 4
    for (int k = 0; k < D; k++) {
        const unsigned long long hg = sh_hg[warp][k];   // LDS.64 broadcast
        const float* w3r = w3 + (size_t)k * D + lane;
        const float* w4r = w4 + (size_t)k * D + lane;
        #pragma unroll
        for (int j = 0; j < 4; j++) {
            unsigned long long wp = pack_f32(__ldg(w3r + 32 * j), __ldg(w4r + 32 * j));
            FMA2(acc[j], hg, wp);
        }
    }
    #pragma unroll
    for (int j = 0; j < 4; j++) {
        const int c = lane + 32 * j;
        float a0, a1;
        unpack_f32(acc[j], a0, a1);
        const float wgt = 1.f / (1.f + __expf(-(a0 + a1)));
        out[(size_t)n * D + c] = (1.f - wgt) * h[j] + wgt * g[j];
    }
}

extern "C" void kernel_launch(void* const* d_in, const int* in_sizes, int n_in,
                              void* d_out, int out_size)
{
    const float* hidden = (const float*)d_in[0];
    const float* nh1    = (const float*)d_in[1];
    const float* nh2    = (const float*)d_in[2];
    const float* nw0    = (const float*)d_in[3];
    const float* nw1    = (const float*)d_in[4];
    const float* w1     = (const float*)d_in[5];
    const float* w2     = (const float*)d_in[6];
    const float* w3     = (const float*)d_in[7];
    const float* w4     = (const float*)d_in[8];
    const float* sv     = (const float*)d_in[9];
    float* out = (float*)d_out;

    const int N0 = in_sizes[0] / D;   // B*L   = 3200
    const int N1 = in_sizes[1] / D;   // B*L*S = 38400

    float *agg_a, *agg_b, *agg_c;
    cudaGetSymbolAddress((void**)&agg_a, g_agg_a);
    cudaGetSymbolAddress((void**)&agg_b, g_agg_b);
    cudaGetSymbolAddress((void**)&agg_c, g_agg_c);

    // hop 1
    agg_kernel<<<N0 / 2, 64>>>(hidden, nh1, nw0, w1, w2, agg_a);
    agg_kernel<<<N1 / 2, 64>>>(nh1,    nh2, nw1, w1, w2, agg_b);
    // hop 2
    agg_kernel<<<N0 / 2, 64>>>(agg_a,  agg_b, nw0, w1, w2, agg_c);
    // gate
    final_kernel<<<N0 / 4, 128>>>(hidden, agg_a, agg_c, w3, w4, sv, out);
}